// round 4
// baseline (speedup 1.0000x reference)
#include <cuda_runtime.h>
#include <cstdint>

// ---------------------------------------------------------------------------
// Problem constants
// ---------------------------------------------------------------------------
#define B_       16
#define M_       100
#define NUM_CLS  80
#define HW_TOT   21824          // 128^2 + 64^2 + 32^2 + 16^2 + 8^2
#define NPIX     (B_ * HW_TOT)  // 349184

#define CLS_N    (NPIX * 82)
#define REG_N    (NPIX * 6)
#define OFF_REG  ((size_t)CLS_N)
#define OFF_IND  (OFF_REG + REG_N)
#define OFF_NB   (OFF_IND + NPIX)

__device__ __constant__ int   c_off[5]   = {0, 16384, 20480, 21504, 21760};
__device__ __constant__ int   c_shift[5] = {7, 6, 5, 4, 3};
__device__ __constant__ float c_stride[5]= {8.f, 16.f, 32.f, 64.f, 128.f};

// ---------------------------------------------------------------------------
// Single fused kernel. grid=(86,16), block=256. Each block covers one
// (batch, level) 256-pixel slab; it computes assignments for its pixels and
// densely writes its own contiguous cls/reg output slabs with float4 stores.
// ---------------------------------------------------------------------------
__global__ __launch_bounds__(256) void fused_kernel(const float* __restrict__ gt,
                                                    float* __restrict__ out)
{
    __shared__ float4 cbnd[M_];    // candidate shrunk bounds (level coords)
    __shared__ float4 cbox[M_];    // candidate image-space box
    __shared__ float  carea[M_];
    __shared__ int    cj[M_];      // original box index
    __shared__ int    clab[M_];
    __shared__ int    s_cnt;
    __shared__ float4 s_reg[256];  // per-pixel (l,t,r,b)/(4*stride) (0 if neg)
    __shared__ float4 s_rec[256];  // per-pixel {soft, labelf, posf, unused}

    const int b  = blockIdx.y;
    const int p0 = blockIdx.x * 256;
    const int t  = threadIdx.x;

    int lev;
    if      (p0 < 16384) lev = 0;
    else if (p0 < 20480) lev = 1;
    else if (p0 < 21504) lev = 2;
    else if (p0 < 21760) lev = 3;
    else                 lev = 4;

    const int   sh  = c_shift[lev];
    const int   fw  = 1 << sh;
    const float fS  = c_stride[lev];
    const float inv = 1.0f / fS;                 // exact (power of two)
    const int   off = c_off[lev];

    const int n_pix = min(256, HW_TOT - p0);     // 64 for last block, else 256

    // block's row range at this level
    const int local0 = p0 - off;
    const int by0 = local0 >> sh;
    const int by1 = (local0 + n_pix - 1) >> sh;

    if (t == 0) s_cnt = 0;
    __syncthreads();

    int validp = 0;
    if (t < M_) {
        const float* bp = gt + (b * M_ + t) * 5;
        float x1 = bp[0], y1 = bp[1], x2 = bp[2], y2 = bp[3];

        float b0 = x1 * inv, b1 = y1 * inv, b2 = x2 * inv, b3 = y2 * inv;
        float cx = (b0 + b2) * 0.5f;
        float cy = (b1 + b3) * 0.5f;
        float hw = (b2 - b0) * 0.5f * 0.2f;
        float hh = (b3 - b1) * 0.5f * 0.2f;
        float px1 = fmaxf(floorf(cx - hw), 0.0f);
        float py1 = fmaxf(floorf(cy - hh), 0.0f);
        float px2 = fminf(ceilf(cx + hw), (float)fw);
        float py2 = fminf(ceilf(cy + hh), (float)fw);

        bool hit = (px2 > px1) && (py2 > py1) &&
                   (py1 <= (float)by1) && (py2 > (float)by0);
        if (hit) {
            int k = atomicAdd(&s_cnt, 1);
            cbnd[k]  = make_float4(px1, py1, px2, py2);
            cbox[k]  = make_float4(x1, y1, x2, y2);
            carea[k] = (x2 - x1) * (y2 - y1);
            cj[k]    = t;
            clab[k]  = (int)bp[4];
        }
        validp = (fabsf(x1) + fabsf(y1) + fabsf(x2) + fabsf(y2) > 0.0f) ? 1 : 0;
    }
    int nvalid = __syncthreads_count(validp);

    if (blockIdx.x == 85 && t == 0)
        out[OFF_NB + b] = (float)nvalid;

    // -------- per-pixel argmin + record --------
    if (t < n_pix) {
        const int   p     = p0 + t;
        const int   local = p - off;
        const int   y     = local >> sh;
        const int   x     = local & (fw - 1);
        const float fx    = (float)x;
        const float fy    = (float)y;

        const int cnt = s_cnt;
        float bestA = 1e7f;
        int   bestK = -1, bestJ = -1;
        for (int k = 0; k < cnt; k++) {
            float4 bb = cbnd[k];
            bool inside = (fx >= bb.x) & (fx < bb.z) & (fy >= bb.y) & (fy < bb.w);
            float a = carea[k];
            int   j = cj[k];
            if (inside && (a < bestA || (a == bestA && j < bestJ))) {
                bestA = a; bestJ = j; bestK = k;
            }
        }

        float4 rg   = make_float4(0.f, 0.f, 0.f, 0.f);
        float  soft = 1.0f;
        float  labf = -1.0f;
        float  posf = 0.0f;
        if (bestK >= 0) {
            float4 wb = cbox[bestK];
            float sx = (fx + 0.5f) * fS;
            float sy = (fy + 0.5f) * fS;
            float l  = sx - wb.x;
            float tt = sy - wb.y;
            float r  = wb.z - sx;
            float bt = wb.w - sy;
            const float eps = 1e-6f;
            float q1 = fminf(fmaxf(fminf(l, r)  / fmaxf(fmaxf(l, r),  eps), 0.f), 1.f);
            float q2 = fminf(fmaxf(fminf(tt, bt)/ fmaxf(fmaxf(tt, bt), eps), 0.f), 1.f);
            soft = sqrtf(q1 * q2);
            labf = (float)clab[bestK];
            posf = 1.0f;
            float inv4 = 0.25f * inv;            // 1/(4*stride), exact
            rg = make_float4(l * inv4, tt * inv4, r * inv4, bt * inv4);
        }
        s_reg[t] = rg;
        s_rec[t] = make_float4(soft, labf, posf, 0.0f);

        const int g = b * HW_TOT + p;
        out[OFF_IND + g] = (bestK >= 0) ? (float)bestJ : -1.0f;
    }
    __syncthreads();

    // -------- dense coalesced slab writes --------
    const int g0 = b * HW_TOT + p0;

    // cls slab: n_pix * 82 floats, contiguous, 16B-aligned (g0 even)
    {
        float4* cls4 = reinterpret_cast<float4*>(out + (size_t)g0 * 82);
        const int n4 = (n_pix * 82) >> 2;
        for (int i = t; i < n4; i += 256) {
            int e  = i << 2;
            int gl = (unsigned)e / 82u;
            int c  = e - gl * 82;
            float4 rec = s_rec[gl];
            float v[4];
#pragma unroll
            for (int k = 0; k < 4; k++) {
                if (c == 82) { gl++; c = 0; rec = s_rec[gl]; }
                v[k] = (c < 80) ? ((c == (int)rec.y) ? 1.0f : 0.0f)
                     : (c == 80) ? rec.x : rec.z;
                c++;
            }
            cls4[i] = make_float4(v[0], v[1], v[2], v[3]);
        }
    }

    // reg slab: n_pix * 6 floats, contiguous, 16B-aligned
    {
        float4* reg4 = reinterpret_cast<float4*>(out + OFF_REG + (size_t)g0 * 6);
        const int n4 = (n_pix * 6) >> 2;
        for (int i = t; i < n4; i += 256) {
            int e  = i << 2;
            int gl = (unsigned)e / 6u;
            int c  = e - gl * 6;
            float v[4];
#pragma unroll
            for (int k = 0; k < 4; k++) {
                if (c == 6) { gl++; c = 0; }
                if (c < 4) {
                    v[k] = reinterpret_cast<const float*>(&s_reg[gl])[c];
                } else if (c == 4) {
                    v[k] = s_rec[gl].x;
                } else {
                    v[k] = s_rec[gl].z;
                }
                c++;
            }
            reg4[i] = make_float4(v[0], v[1], v[2], v[3]);
        }
    }
}

// ---------------------------------------------------------------------------
extern "C" void kernel_launch(void* const* d_in, const int* in_sizes, int n_in,
                              void* d_out, int out_size)
{
    const float* gt  = (const float*)d_in[0];
    float*       out = (float*)d_out;

    dim3 grid((HW_TOT + 255) / 256, B_);           // (86, 16)
    fused_kernel<<<grid, 256>>>(gt, out);
}

// round 5
// speedup vs baseline: 1.2264x; 1.2264x over previous
#include <cuda_runtime.h>
#include <cstdint>

// ---------------------------------------------------------------------------
// Problem constants
// ---------------------------------------------------------------------------
#define B_       16
#define M_       100
#define NUM_CLS  80
#define HW_TOT   21824          // 128^2 + 64^2 + 32^2 + 16^2 + 8^2
#define NPIX     (B_ * HW_TOT)  // 349184

#define CLS_N    (NPIX * 82)
#define REG_N    (NPIX * 6)
#define OFF_REG  ((size_t)CLS_N)
#define OFF_IND  (OFF_REG + REG_N)
#define OFF_NB   (OFF_IND + NPIX)

__device__ __constant__ int   c_off[5]   = {0, 16384, 20480, 21504, 21760};
__device__ __constant__ int   c_shift[5] = {7, 6, 5, 4, 3};
__device__ __constant__ float c_stride[5]= {8.f, 16.f, 32.f, 64.f, 128.f};

// ---------------------------------------------------------------------------
// Single fused kernel. grid=(86,16), block=256. Each block covers one
// (batch, level) 256-pixel slab. Phase A: build per-block candidate list AND
// stream zeros over the block's contiguous cls slab (pure STG.128). Barrier.
// Phase B: per-pixel argmin; each pixel thread writes only its few nonzero
// cls floats, its 6 reg floats, and its ind value.
// ---------------------------------------------------------------------------
__global__ __launch_bounds__(256) void fused_kernel(const float* __restrict__ gt,
                                                    float* __restrict__ out)
{
    __shared__ float4 cbnd[M_];    // candidate shrunk bounds (level coords)
    __shared__ float4 cbox[M_];    // candidate image-space box
    __shared__ float  carea[M_];
    __shared__ int    cj[M_];      // original box index
    __shared__ int    clab[M_];
    __shared__ int    s_cnt;

    const int b  = blockIdx.y;
    const int p0 = blockIdx.x * 256;
    const int t  = threadIdx.x;

    int lev;
    if      (p0 < 16384) lev = 0;
    else if (p0 < 20480) lev = 1;
    else if (p0 < 21504) lev = 2;
    else if (p0 < 21760) lev = 3;
    else                 lev = 4;

    const int   sh  = c_shift[lev];
    const int   fw  = 1 << sh;
    const float fS  = c_stride[lev];
    const float inv = 1.0f / fS;                 // exact (power of two)
    const int   off = c_off[lev];

    const int n_pix = min(256, HW_TOT - p0);     // 64 for last block, else 256
    const int g0    = b * HW_TOT + p0;

    const int local0 = p0 - off;
    const int by0 = local0 >> sh;
    const int by1 = (local0 + n_pix - 1) >> sh;

    if (t == 0) s_cnt = 0;
    __syncthreads();

    // ---- Phase A: candidate build (threads < M_) ----
    int validp = 0;
    if (t < M_) {
        const float* bp = gt + (b * M_ + t) * 5;
        float x1 = bp[0], y1 = bp[1], x2 = bp[2], y2 = bp[3];

        float b0 = x1 * inv, b1 = y1 * inv, b2 = x2 * inv, b3 = y2 * inv;
        float cx = (b0 + b2) * 0.5f;
        float cy = (b1 + b3) * 0.5f;
        float hw = (b2 - b0) * 0.5f * 0.2f;
        float hh = (b3 - b1) * 0.5f * 0.2f;
        float px1 = fmaxf(floorf(cx - hw), 0.0f);
        float py1 = fmaxf(floorf(cy - hh), 0.0f);
        float px2 = fminf(ceilf(cx + hw), (float)fw);
        float py2 = fminf(ceilf(cy + hh), (float)fw);

        bool hit = (px2 > px1) && (py2 > py1) &&
                   (py1 <= (float)by1) && (py2 > (float)by0);
        if (hit) {
            int k = atomicAdd(&s_cnt, 1);
            cbnd[k]  = make_float4(px1, py1, px2, py2);
            cbox[k]  = make_float4(x1, y1, x2, y2);
            carea[k] = (x2 - x1) * (y2 - y1);
            cj[k]    = t;
            clab[k]  = (int)bp[4];
        }
        validp = (fabsf(x1) + fabsf(y1) + fabsf(x2) + fabsf(y2) > 0.0f) ? 1 : 0;
    }

    // ---- Phase A: stream zeros over this block's cls slab (all threads) ----
    {
        float4* cls4 = reinterpret_cast<float4*>(out + (size_t)g0 * 82);
        const int n4 = (n_pix * 82) >> 2;        // 5248 (or 1312 last block)
        const float4 z = make_float4(0.f, 0.f, 0.f, 0.f);
        for (int i = t; i < n4; i += 256)
            cls4[i] = z;
    }

    // barrier: publishes candidates AND orders zero-stores before fix-ups
    int nvalid = __syncthreads_count(validp);

    if (blockIdx.x == 85 && t == 0)
        out[OFF_NB + b] = (float)nvalid;

    // ---- Phase B: per-pixel argmin + sparse fix-up writes ----
    if (t < n_pix) {
        const int   p     = p0 + t;
        const int   local = p - off;
        const int   y     = local >> sh;
        const int   x     = local & (fw - 1);
        const float fx    = (float)x;
        const float fy    = (float)y;

        const int cnt = s_cnt;
        float bestA = 1e7f;
        int   bestK = -1, bestJ = -1;
        for (int k = 0; k < cnt; k++) {
            float4 bb = cbnd[k];
            bool inside = (fx >= bb.x) & (fx < bb.z) & (fy >= bb.y) & (fy < bb.w);
            float a = carea[k];
            int   j = cj[k];
            if (inside && (a < bestA || (a == bestA && j < bestJ))) {
                bestA = a; bestJ = j; bestK = k;
            }
        }

        const int    g  = g0 + t;
        const size_t cb = (size_t)g * 82;
        float2* rp = reinterpret_cast<float2*>(out + OFF_REG + (size_t)g * 6);

        float soft = 1.0f, posf = 0.0f;
        float4 rg = make_float4(0.f, 0.f, 0.f, 0.f);

        if (bestK >= 0) {
            float4 wb = cbox[bestK];
            float sx = (fx + 0.5f) * fS;
            float sy = (fy + 0.5f) * fS;
            float l  = sx - wb.x;
            float tt = sy - wb.y;
            float r  = wb.z - sx;
            float bt = wb.w - sy;
            const float eps = 1e-6f;
            float q1 = fminf(fmaxf(fminf(l, r)  / fmaxf(fmaxf(l, r),  eps), 0.f), 1.f);
            float q2 = fminf(fmaxf(fminf(tt, bt)/ fmaxf(fmaxf(tt, bt), eps), 0.f), 1.f);
            soft = sqrtf(q1 * q2);
            posf = 1.0f;
            float inv4 = 0.25f * inv;            // 1/(4*stride), exact
            rg = make_float4(l * inv4, tt * inv4, r * inv4, bt * inv4);

            out[cb + clab[bestK]] = 1.0f;        // one-hot (after zero pass)
        }

        *reinterpret_cast<float2*>(out + cb + 80) = make_float2(soft, posf);

        rp[0] = make_float2(rg.x, rg.y);
        rp[1] = make_float2(rg.z, rg.w);
        rp[2] = make_float2(soft, posf);

        out[OFF_IND + g] = (bestK >= 0) ? (float)bestJ : -1.0f;
    }
}

// ---------------------------------------------------------------------------
extern "C" void kernel_launch(void* const* d_in, const int* in_sizes, int n_in,
                              void* d_out, int out_size)
{
    const float* gt  = (const float*)d_in[0];
    float*       out = (float*)d_out;

    dim3 grid((HW_TOT + 255) / 256, B_);           // (86, 16)
    fused_kernel<<<grid, 256>>>(gt, out);
}

// round 7
// speedup vs baseline: 1.2308x; 1.0036x over previous
#include <cuda_runtime.h>
#include <cstdint>

// ---------------------------------------------------------------------------
// Problem constants
// ---------------------------------------------------------------------------
#define B_       16
#define M_       100
#define NUM_CLS  80
#define HW_TOT   21824          // 128^2 + 64^2 + 32^2 + 16^2 + 8^2
#define NPIX     (B_ * HW_TOT)  // 349184

#define CLS_N    (NPIX * 82)
#define REG_N    (NPIX * 6)
#define OFF_REG  ((size_t)CLS_N)
#define OFF_IND  (OFF_REG + REG_N)
#define OFF_NB   (OFF_IND + NPIX)

__device__ __constant__ int   c_off[5]   = {0, 16384, 20480, 21504, 21760};
__device__ __constant__ int   c_shift[5] = {7, 6, 5, 4, 3};
__device__ __constant__ float c_stride[5]= {8.f, 16.f, 32.f, 64.f, 128.f};

// ---------------------------------------------------------------------------
// Single fused kernel. grid=(86,16), block=256. Each block = one (batch,level)
// 256-pixel slab.
//   Phase A: per-block candidate compaction (threads < M_).
//   Phase B: per-pixel argmin -> records in smem; coalesced ind write.
//   Phase C: dense slab writes, every sector touched exactly once:
//            cls = zero float4 stream with {soft,posf} merged into the one
//            float4 per row that covers cols 80/81; reg = aligned smem copy.
//   Phase D: one-hot scatter (only positives), ordered after C by barrier.
// ---------------------------------------------------------------------------
__global__ __launch_bounds__(256) void fused_kernel(const float* __restrict__ gt,
                                                    float* __restrict__ out)
{
    __shared__ float4 cbnd[M_];    // candidate shrunk bounds (level coords)
    __shared__ float4 cbox[M_];    // candidate image-space box
    __shared__ float  carea[M_];
    __shared__ int    cj[M_];      // original box index
    __shared__ int    clab[M_];
    __shared__ int    s_cnt;
    __shared__ alignas(16) float2 s_sp[256];      // per-pixel {soft, posf}
    __shared__ alignas(16) float  s_r6[256 * 6];  // reg records, output layout

    const int b  = blockIdx.y;
    const int p0 = blockIdx.x * 256;
    const int t  = threadIdx.x;

    int lev;
    if      (p0 < 16384) lev = 0;
    else if (p0 < 20480) lev = 1;
    else if (p0 < 21504) lev = 2;
    else if (p0 < 21760) lev = 3;
    else                 lev = 4;

    const int   sh  = c_shift[lev];
    const int   fw  = 1 << sh;
    const float fS  = c_stride[lev];
    const float inv = 1.0f / fS;                 // exact (power of two)
    const int   off = c_off[lev];

    const int n_pix = min(256, HW_TOT - p0);     // 64 for last block, else 256
    const int g0    = b * HW_TOT + p0;

    const int local0 = p0 - off;
    const int by0 = local0 >> sh;
    const int by1 = (local0 + n_pix - 1) >> sh;

    if (t == 0) s_cnt = 0;
    __syncthreads();

    // ---- Phase A: candidate build ----
    int validp = 0;
    if (t < M_) {
        const float* bp = gt + (b * M_ + t) * 5;
        float x1 = bp[0], y1 = bp[1], x2 = bp[2], y2 = bp[3];

        float b0 = x1 * inv, b1 = y1 * inv, b2 = x2 * inv, b3 = y2 * inv;
        float cx = (b0 + b2) * 0.5f;
        float cy = (b1 + b3) * 0.5f;
        float hw = (b2 - b0) * 0.5f * 0.2f;
        float hh = (b3 - b1) * 0.5f * 0.2f;
        float px1 = fmaxf(floorf(cx - hw), 0.0f);
        float py1 = fmaxf(floorf(cy - hh), 0.0f);
        float px2 = fminf(ceilf(cx + hw), (float)fw);
        float py2 = fminf(ceilf(cy + hh), (float)fw);

        bool hit = (px2 > px1) && (py2 > py1) &&
                   (py1 <= (float)by1) && (py2 > (float)by0);
        if (hit) {
            int k = atomicAdd(&s_cnt, 1);
            cbnd[k]  = make_float4(px1, py1, px2, py2);
            cbox[k]  = make_float4(x1, y1, x2, y2);
            carea[k] = (x2 - x1) * (y2 - y1);
            cj[k]    = t;
            clab[k]  = (int)bp[4];
        }
        validp = (fabsf(x1) + fabsf(y1) + fabsf(x2) + fabsf(y2) > 0.0f) ? 1 : 0;
    }
    int nvalid = __syncthreads_count(validp);

    if (blockIdx.x == 85 && t == 0)
        out[OFF_NB + b] = (float)nvalid;

    // ---- Phase B: per-pixel argmin -> smem records (+ coalesced ind) ----
    int lab = -1;                                 // kept in registers for D
    if (t < n_pix) {
        const int   p     = p0 + t;
        const int   local = p - off;
        const int   y     = local >> sh;
        const int   x     = local & (fw - 1);
        const float fx    = (float)x;
        const float fy    = (float)y;

        const int cnt = s_cnt;
        float bestA = 1e7f;
        int   bestK = -1, bestJ = -1;
        for (int k = 0; k < cnt; k++) {
            float4 bb = cbnd[k];
            bool inside = (fx >= bb.x) & (fx < bb.z) & (fy >= bb.y) & (fy < bb.w);
            float a = carea[k];
            int   j = cj[k];
            if (inside && (a < bestA || (a == bestA && j < bestJ))) {
                bestA = a; bestJ = j; bestK = k;
            }
        }

        float soft = 1.0f, posf = 0.0f;
        float4 rg = make_float4(0.f, 0.f, 0.f, 0.f);
        if (bestK >= 0) {
            float4 wb = cbox[bestK];
            float sx = (fx + 0.5f) * fS;
            float sy = (fy + 0.5f) * fS;
            float l  = sx - wb.x;
            float tt = sy - wb.y;
            float r  = wb.z - sx;
            float bt = wb.w - sy;
            const float eps = 1e-6f;
            float q1 = fminf(fmaxf(fminf(l, r)  / fmaxf(fmaxf(l, r),  eps), 0.f), 1.f);
            float q2 = fminf(fmaxf(fminf(tt, bt)/ fmaxf(fmaxf(tt, bt), eps), 0.f), 1.f);
            soft = sqrtf(q1 * q2);
            posf = 1.0f;
            lab  = clab[bestK];
            float inv4 = 0.25f * inv;             // 1/(4*stride), exact
            rg = make_float4(l * inv4, tt * inv4, r * inv4, bt * inv4);
        }
        s_sp[t] = make_float2(soft, posf);
        float* r6 = s_r6 + t * 6;
        r6[0] = rg.x; r6[1] = rg.y; r6[2] = rg.z; r6[3] = rg.w;
        r6[4] = soft; r6[5] = posf;

        out[OFF_IND + g0 + t] = (bestK >= 0) ? (float)bestJ : -1.0f;
    }
    __syncthreads();

    // ---- Phase C: dense slab writes, one touch per sector ----
    // cls: zero stream with {soft,posf} merged. Row length 82 (= 2 mod 4), so
    // even rows: float4 at c==80 is {s,p, next-row c0,c1 = 0,0};
    // odd  rows: float4 at c==78 is {0,0, s,p}. (One-hot patched in Phase D.)
    {
        float4* cls4 = reinterpret_cast<float4*>(out + (size_t)g0 * 82);
        const int n4 = (n_pix * 82) >> 2;
        for (int i = t; i < n4; i += 256) {
            int e  = i << 2;
            unsigned gl = (unsigned)e / 82u;
            int c  = e - (int)gl * 82;
            float4 v = make_float4(0.f, 0.f, 0.f, 0.f);
            if (c == 80) { float2 sp = s_sp[gl]; v.x = sp.x; v.y = sp.y; }
            if (c == 78) { float2 sp = s_sp[gl]; v.z = sp.x; v.w = sp.y; }
            cls4[i] = v;
        }
    }
    // reg: smem layout == output layout -> aligned 16B copy
    {
        float4* reg4 = reinterpret_cast<float4*>(out + OFF_REG + (size_t)g0 * 6);
        const float4* sr4 = reinterpret_cast<const float4*>(s_r6);
        const int n4 = (n_pix * 6) >> 2;
        for (int i = t; i < n4; i += 256)
            reg4[i] = sr4[i];
    }
    __syncthreads();   // order dense cls stores before one-hot patches

    // ---- Phase D: one-hot scatter (positives only) ----
    if (t < n_pix && lab >= 0)
        out[(size_t)(g0 + t) * 82 + lab] = 1.0f;
}

// ---------------------------------------------------------------------------
extern "C" void kernel_launch(void* const* d_in, const int* in_sizes, int n_in,
                              void* d_out, int out_size)
{
    const float* gt  = (const float*)d_in[0];
    float*       out = (float*)d_out;

    dim3 grid((HW_TOT + 255) / 256, B_);           // (86, 16)
    fused_kernel<<<grid, 256>>>(gt, out);
}